// round 16
// baseline (speedup 1.0000x reference)
#include <cuda_runtime.h>

#define NN   50000
#define NG   32
#define NF   16
#define GF   2
#define HID  300
#define LATD 100
#define NE   800000
#define TE   64
#define STR  65   // smem row stride (odd: 2-way max conflict on strided access)

typedef unsigned long long u64;
typedef long long i64;

// -------- scratch (device globals; no allocation allowed) --------
__device__ float g_B[NN * HID];     // per-node  x @ W_bot
__device__ float g_C[NN * HID];     // per-node  x @ (W_top - W_bot) + b1
__device__ float g_acc[NN * LATD];  // scatter accumulator
__device__ float g_x1[NN * LATD];   // node features between layers
__device__ float g_cnt[NN];         // in-degree (float for direct divide)
__device__ float g_pool[NG * LATD]; // graph pooling sums
__device__ float g_gcnt[NG];        // nodes per graph
__device__ int   g_src[NE];         // normalized int32 edge sources
__device__ int   g_dst[NE];         // normalized int32 edge dests
__device__ int   g_batch[NN];       // normalized int32 batch ids
__device__ int   g_is64;            // dtype probe result

// -------- f32x2 helpers (FFMA2: 2x FP32 FMA throughput, PTX-only) --------
__device__ __forceinline__ u64 splat2(float v) {
    u64 r; unsigned iv = __float_as_uint(v);
    asm("mov.b64 %0, {%1, %1};" : "=l"(r) : "r"(iv));
    return r;
}
__device__ __forceinline__ u64 fma2(u64 a, u64 b, u64 c) {
    u64 d;
    asm("fma.rn.f32x2 %0, %1, %2, %3;" : "=l"(d) : "l"(a), "l"(b), "l"(c));
    return d;
}
__device__ __forceinline__ void unpack2(u64 v, float& lo, float& hi) {
    unsigned a, b;
    asm("mov.b64 {%0, %1}, %2;" : "=r"(a), "=r"(b) : "l"(v));
    lo = __uint_as_float(a); hi = __uint_as_float(b);
}

// -------- dtype probe: are index inputs int64 or int32? --------
__global__ void k_probe(const void* ei) {
    const u64* p = (const u64*)ei;
    int is64 = 1;
    for (int i = 0; i < 16; i++)
        if (p[i] >= (1ull << 32)) is64 = 0;
    g_is64 = is64;
}

__global__ void k_convert(const void* ei, const void* batch) {
    int i = blockIdx.x * blockDim.x + threadIdx.x;
    if (g_is64) {
        const i64* e = (const i64*)ei;
        const i64* b = (const i64*)batch;
        if (i < NE) { g_src[i] = (int)e[i]; g_dst[i] = (int)e[NE + i]; }
        if (i < NN) g_batch[i] = (int)b[i];
    } else {
        const int* e = (const int*)ei;
        const int* b = (const int*)batch;
        if (i < NE) { g_src[i] = e[i]; g_dst[i] = e[NE + i]; }
        if (i < NN) g_batch[i] = b[i];
    }
}

// -------- zero / count kernels --------
__global__ void k_zero_all() {
    int i = blockIdx.x * blockDim.x + threadIdx.x;
    int st = gridDim.x * blockDim.x;
    for (int j = i; j < NN * LATD; j += st) g_acc[j] = 0.f;
    for (int j = i; j < NN; j += st) g_cnt[j] = 0.f;
    for (int j = i; j < NG * LATD; j += st) g_pool[j] = 0.f;
    for (int j = i; j < NG; j += st) g_gcnt[j] = 0.f;
}
__global__ void k_counts() {
    int i = blockIdx.x * blockDim.x + threadIdx.x;
    if (i < NE) atomicAdd(&g_cnt[g_dst[i]], 1.f);
    if (i < NN) atomicAdd(&g_gcnt[g_batch[i]], 1.f);
}

// -------- tiled node precompute: 24 nodes/CTA, w1 float4 reused across 8 nodes --------
// B = x@W_bot, C = x@(W_top - W_bot) + b1
template <int INF>
__global__ void __launch_bounds__(256) k_node_pre2(const float* __restrict__ x,
                                                   const float* __restrict__ w1,
                                                   const float* __restrict__ b1) {
    __shared__ float sx[24 * INF];
    const int tid = threadIdx.x;
    const int n0 = blockIdx.x * 24;
    for (int i = tid; i < 24 * INF; i += 256) {
        int n = i / INF, f = i - n * INF;
        sx[i] = (n0 + n < NN) ? x[(n0 + n) * INF + f] : 0.f;
    }
    __syncthreads();
    const int j = tid % 75, g = tid / 75;   // 3 groups x 75 threads (225 active)
    if (g >= 3) return;
    const int h4 = j * 4;
    float4 at[8], ab[8];
#pragma unroll
    for (int nn = 0; nn < 8; nn++) {
        at[nn] = make_float4(0.f, 0.f, 0.f, 0.f);
        ab[nn] = make_float4(0.f, 0.f, 0.f, 0.f);
    }
#pragma unroll 4
    for (int f = 0; f < INF; f++) {
        float4 wt = __ldg((const float4*)(w1 + f * HID + h4));
        float4 wb = __ldg((const float4*)(w1 + (INF + f) * HID + h4));
#pragma unroll
        for (int nn = 0; nn < 8; nn++) {
            float xv = sx[(g * 8 + nn) * INF + f];
            at[nn].x = fmaf(xv, wt.x, at[nn].x); at[nn].y = fmaf(xv, wt.y, at[nn].y);
            at[nn].z = fmaf(xv, wt.z, at[nn].z); at[nn].w = fmaf(xv, wt.w, at[nn].w);
            ab[nn].x = fmaf(xv, wb.x, ab[nn].x); ab[nn].y = fmaf(xv, wb.y, ab[nn].y);
            ab[nn].z = fmaf(xv, wb.z, ab[nn].z); ab[nn].w = fmaf(xv, wb.w, ab[nn].w);
        }
    }
    float4 bb = __ldg((const float4*)(b1 + h4));
#pragma unroll
    for (int nn = 0; nn < 8; nn++) {
        int node = n0 + g * 8 + nn;
        if (node < NN) {
            int o = node * HID + h4;
            *(float4*)(g_B + o) = ab[nn];
            float4 c = make_float4(at[nn].x - ab[nn].x + bb.x, at[nn].y - ab[nn].y + bb.y,
                                   at[nn].z - ab[nn].z + bb.z, at[nn].w - ab[nn].w + bb.w);
            *(float4*)(g_C + o) = c;
        }
    }
}

// -------- fused edge MLP: 64 edges/CTA, 512 threads, shA reused for h2^T --------
// smem: idx(128) + shA[300][65] + shB weight staging(2x3200)  => 104112 B => 16 warps/SM
__global__ void __launch_bounds__(512) k_edge(const float* __restrict__ w2,
                                              const float* __restrict__ b2,
                                              const float* __restrict__ w3,
                                              const float* __restrict__ b3) {
    extern __shared__ float smem[];
    int* s_src = (int*)smem;            // 64 ints
    int* s_dst = s_src + TE;            // 64 ints
    float* shA = smem + 128;            // [300][65]: h1^T, later h2^T
    float* shB = shA + HID * STR;       // 6400 floats weight staging

    const int tid = threadIdx.x;
    const int tx = tid & 31;
    const int row0 = (tid >> 5) * 4;    // 16 warps -> rows 0..63, 4 per thread
    const int e0 = blockIdx.x * TE;

    if (tid < TE) {
        s_src[tid] = g_src[e0 + tid];
        s_dst[tid] = g_dst[e0 + tid];
    }
    __syncthreads();

    // gather: h1^T[k][r] = relu(C[dst_r][k] + B[src_r][k])
    for (int idx = tid; idx < TE * (HID / 2); idx += 512) {
        int r = idx / (HID / 2);
        int k2 = (idx - r * (HID / 2)) * 2;
        const float2 cv = *(const float2*)(g_C + s_dst[r] * HID + k2);
        const float2 bv = *(const float2*)(g_B + s_src[r] * HID + k2);
        shA[k2 * STR + r]       = fmaxf(cv.x + bv.x, 0.f);
        shA[(k2 + 1) * STR + r] = fmaxf(cv.y + bv.y, 0.f);
    }
    __syncthreads();

    // ---------------- GEMM1: [64,300] @ w2[300,300] (cols padded to 320) ----------------
    // thread tile: 4 rows x 10 cols (5 col-pairs at stride 64)
    u64 acc[4][5];
#pragma unroll
    for (int r = 0; r < 4; r++)
#pragma unroll
        for (int t = 0; t < 5; t++) acc[r][t] = 0ull;

    float sreg[7];
#pragma unroll
    for (int q = 0; q < 7; q++) {
        int i2 = tid + 512 * q;
        if (i2 < 3200) {
            int kk = i2 / 320, j = i2 - kk * 320;
            sreg[q] = (j < HID) ? __ldg(w2 + kk * HID + j) : 0.f;
        }
    }
#pragma unroll
    for (int q = 0; q < 7; q++) {
        int i2 = tid + 512 * q;
        if (i2 < 3200) shB[i2] = sreg[q];
    }
    __syncthreads();

    int buf = 0;
#pragma unroll 1
    for (int kc = 0; kc < 30; kc++) {
        int k0 = kc * 10;
        if (kc < 29) {
            int kn = k0 + 10;
#pragma unroll
            for (int q = 0; q < 7; q++) {
                int i2 = tid + 512 * q;
                if (i2 < 3200) {
                    int kk = i2 / 320, j = i2 - kk * 320;
                    sreg[q] = (j < HID) ? __ldg(w2 + (kn + kk) * HID + j) : 0.f;
                }
            }
        }
        const float* bBase = shB + buf * 3200;
#pragma unroll
        for (int kk = 0; kk < 10; kk++) {
            const float* aR = shA + (k0 + kk) * STR + row0;
            u64 s0 = splat2(aR[0]), s1 = splat2(aR[1]);
            u64 s2 = splat2(aR[2]), s3 = splat2(aR[3]);
            const float* bR = bBase + kk * 320 + tx * 2;
#pragma unroll
            for (int t = 0; t < 5; t++) {
                u64 bv = *(const u64*)(bR + 64 * t);
                acc[0][t] = fma2(s0, bv, acc[0][t]);
                acc[1][t] = fma2(s1, bv, acc[1][t]);
                acc[2][t] = fma2(s2, bv, acc[2][t]);
                acc[3][t] = fma2(s3, bv, acc[3][t]);
            }
        }
        if (kc < 29) {
#pragma unroll
            for (int q = 0; q < 7; q++) {
                int i2 = tid + 512 * q;
                if (i2 < 3200) shB[(buf ^ 1) * 3200 + i2] = sreg[q];
            }
        }
        __syncthreads();
        buf ^= 1;
    }

    // epilogue GEMM1: write h2^T = relu(acc + b2) back into shA (h1^T is dead)
#pragma unroll
    for (int t = 0; t < 5; t++) {
        int j0 = 64 * t + tx * 2;
        if (j0 < HID) {     // j0 even, j0+1 <= 299
            float bb0 = __ldg(b2 + j0), bb1 = __ldg(b2 + j0 + 1);
#pragma unroll
            for (int r = 0; r < 4; r++) {
                float lo, hi; unpack2(acc[r][t], lo, hi);
                shA[j0 * STR + row0 + r]       = fmaxf(lo + bb0, 0.f);
                shA[(j0 + 1) * STR + row0 + r] = fmaxf(hi + bb1, 0.f);
            }
        }
    }

    // prefetch GEMM2 chunk 0 into registers while epilogue drains
    float sreg2[3];
#pragma unroll
    for (int q = 0; q < 3; q++) {
        int i2 = tid + 512 * q;
        if (i2 < 1280) {
            int kk = i2 / 128, j = i2 - kk * 128;
            sreg2[q] = (j < LATD) ? __ldg(w3 + kk * LATD + j) : 0.f;
        }
    }
    __syncthreads();   // shA (h2^T) writes + shB reads complete
#pragma unroll
    for (int q = 0; q < 3; q++) {
        int i2 = tid + 512 * q;
        if (i2 < 1280) shB[i2] = sreg2[q];
    }
    __syncthreads();

    // ---------------- GEMM2: [64,300] @ w3[300,100] (cols padded to 128) ----------------
    u64 accB[4][2];
#pragma unroll
    for (int r = 0; r < 4; r++)
#pragma unroll
        for (int t = 0; t < 2; t++) accB[r][t] = 0ull;

    buf = 0;
#pragma unroll 1
    for (int kc = 0; kc < 30; kc++) {
        int k0 = kc * 10;
        if (kc < 29) {
            int kn = k0 + 10;
#pragma unroll
            for (int q = 0; q < 3; q++) {
                int i2 = tid + 512 * q;
                if (i2 < 1280) {
                    int kk = i2 / 128, j = i2 - kk * 128;
                    sreg2[q] = (j < LATD) ? __ldg(w3 + (kn + kk) * LATD + j) : 0.f;
                }
            }
        }
        const float* bBase = shB + buf * 1280;
#pragma unroll
        for (int kk = 0; kk < 10; kk++) {
            const float* aR = shA + (k0 + kk) * STR + row0;
            u64 s0 = splat2(aR[0]), s1 = splat2(aR[1]);
            u64 s2 = splat2(aR[2]), s3 = splat2(aR[3]);
            const float* bR = bBase + kk * 128 + tx * 2;
#pragma unroll
            for (int t = 0; t < 2; t++) {
                u64 bv = *(const u64*)(bR + 64 * t);
                accB[0][t] = fma2(s0, bv, accB[0][t]);
                accB[1][t] = fma2(s1, bv, accB[1][t]);
                accB[2][t] = fma2(s2, bv, accB[2][t]);
                accB[3][t] = fma2(s3, bv, accB[3][t]);
            }
        }
        if (kc < 29) {
#pragma unroll
            for (int q = 0; q < 3; q++) {
                int i2 = tid + 512 * q;
                if (i2 < 1280) shB[(buf ^ 1) * 1280 + i2] = sreg2[q];
            }
        }
        __syncthreads();
        buf ^= 1;
    }

    // epilogue GEMM2: m = acc + b3, atomic scatter-sum to g_acc[dst]
#pragma unroll
    for (int t = 0; t < 2; t++) {
        int j0 = 64 * t + tx * 2;
        if (j0 < LATD) {    // j0 even, j0+1 <= 99
            float bb0 = __ldg(b3 + j0), bb1 = __ldg(b3 + j0 + 1);
#pragma unroll
            for (int r = 0; r < 4; r++) {
                float lo, hi; unpack2(accB[r][t], lo, hi);
                int d = s_dst[row0 + r];
                atomicAdd(g_acc + d * LATD + j0,     lo + bb0);
                atomicAdd(g_acc + d * LATD + j0 + 1, hi + bb1);
            }
        }
    }
}

// -------- finalize: scatter-mean + relu (+ re-zero acc for next layer) --------
__global__ void k_fin0() {
    int i = blockIdx.x * blockDim.x + threadIdx.x;
    if (i >= NN * LATD) return;
    int n = i / LATD;
    float v = g_acc[i] / fmaxf(g_cnt[n], 1.f);
    g_x1[i] = fmaxf(v, 0.f);
    g_acc[i] = 0.f;
}
__global__ void k_fin1() {
    int i = blockIdx.x * blockDim.x + threadIdx.x;
    if (i >= NN * LATD) return;
    int n = i / LATD;
    int j = i - n * LATD;
    float v = fmaxf(g_acc[i] / fmaxf(g_cnt[n], 1.f), 0.f);
    atomicAdd(g_pool + g_batch[n] * LATD + j, v);
}

// -------- head MLP: [32,102] -> 100 -> 100 -> 1 (single CTA) --------
__global__ void k_head(const float* __restrict__ u,
                       const float* __restrict__ w1, const float* __restrict__ b1,
                       const float* __restrict__ w2, const float* __restrict__ b2,
                       const float* __restrict__ w3, const float* __restrict__ b3,
                       float* __restrict__ out) {
    __shared__ float sp[NG][LATD + GF];
    __shared__ float sh[NG][LATD];
    __shared__ float sh2[NG][LATD];
    int tid = threadIdx.x;  // 128
    for (int i = tid; i < NG * LATD; i += 128) {
        int g = i / LATD, j = i - g * LATD;
        sp[g][j] = g_pool[i] / fmaxf(g_gcnt[g], 1.f);
    }
    for (int i = tid; i < NG * GF; i += 128) {
        int g = i / GF;
        sp[g][LATD + (i - g * GF)] = u[i];
    }
    __syncthreads();
    for (int i = tid; i < NG * LATD; i += 128) {
        int g = i / LATD, j = i - g * LATD;
        float s = __ldg(b1 + j);
        for (int f = 0; f < LATD + GF; f++) s = fmaf(sp[g][f], __ldg(w1 + f * LATD + j), s);
        sh[g][j] = fmaxf(s, 0.f);
    }
    __syncthreads();
    for (int i = tid; i < NG * LATD; i += 128) {
        int g = i / LATD, j = i - g * LATD;
        float s = __ldg(b2 + j);
        for (int f = 0; f < LATD; f++) s = fmaf(sh[g][f], __ldg(w2 + f * LATD + j), s);
        sh2[g][j] = fmaxf(s, 0.f);
    }
    __syncthreads();
    for (int g = tid; g < NG; g += 128) {
        float s = __ldg(b3);
        for (int f = 0; f < LATD; f++) s = fmaf(sh2[g][f], __ldg(w3 + f), s);
        out[g] = s;
    }
}

extern "C" void kernel_launch(void* const* d_in, const int* in_sizes, int n_in,
                              void* d_out, int out_size) {
    const float* x     = (const float*)d_in[0];
    const void*  ei    = d_in[1];
    const void*  batch = d_in[2];
    const float* u     = (const float*)d_in[3];
    const float* l0w1  = (const float*)d_in[4];
    const float* l0b1  = (const float*)d_in[5];
    const float* l0w2  = (const float*)d_in[6];
    const float* l0b2  = (const float*)d_in[7];
    const float* l0w3  = (const float*)d_in[8];
    const float* l0b3  = (const float*)d_in[9];
    const float* l1w1  = (const float*)d_in[10];
    const float* l1b1  = (const float*)d_in[11];
    const float* l1w2  = (const float*)d_in[12];
    const float* l1b2  = (const float*)d_in[13];
    const float* l1w3  = (const float*)d_in[14];
    const float* l1b3  = (const float*)d_in[15];
    const float* lw1   = (const float*)d_in[16];
    const float* lb1   = (const float*)d_in[17];
    const float* lw2   = (const float*)d_in[18];
    const float* lb2   = (const float*)d_in[19];
    const float* lw3   = (const float*)d_in[20];
    const float* lb3   = (const float*)d_in[21];
    float* out = (float*)d_out;

    const int SMEM_EDGE = (128 + HID * STR + 6400) * (int)sizeof(float); // 104112 B
    cudaFuncSetAttribute(k_edge, cudaFuncAttributeMaxDynamicSharedMemorySize, SMEM_EDGE);

    float* x1p = nullptr;
    cudaGetSymbolAddress((void**)&x1p, g_x1);

    const int NPRE_GRID = (NN + 23) / 24;

    k_probe<<<1, 1>>>(ei);
    k_convert<<<(NE + 255) / 256, 256>>>(ei, batch);
    k_zero_all<<<512, 256>>>();
    k_counts<<<(NE + 255) / 256, 256>>>();
    k_node_pre2<NF><<<NPRE_GRID, 256>>>(x, l0w1, l0b1);
    k_edge<<<NE / TE, 512, SMEM_EDGE>>>(l0w2, l0b2, l0w3, l0b3);
    k_fin0<<<(NN * LATD + 255) / 256, 256>>>();
    k_node_pre2<LATD><<<NPRE_GRID, 256>>>(x1p, l1w1, l1b1);
    k_edge<<<NE / TE, 512, SMEM_EDGE>>>(l1w2, l1b2, l1w3, l1b3);
    k_fin1<<<(NN * LATD + 255) / 256, 256>>>();
    k_head<<<1, 128>>>(u, lw1, lb1, lw2, lb2, lw3, lb3, out);
}